// round 4
// baseline (speedup 1.0000x reference)
#include <cuda_runtime.h>
#include <cuda_bf16.h>

#define NX 1024
#define NY 1024
#define DIMK 128

typedef unsigned long long ull;

// Scratch (device globals — allocation-free per harness rules)
__device__ float g_s[NX * NY];      // 4 MB distance matrix (L2-resident)
__device__ float g_bmax[256];       // per-dist-block min distance (=> global max s = -min)
__device__ float g_M;               // global min distance (broadcast by k_sums)
__device__ float g_rsum[NX];        // row sumexp
__device__ float g_csum[NY];        // col sumexp (atomic accum; zeroed by k_dist)
__device__ float g_p1[NX], g_p2[NX];// per-row partials of S1=sum(a), S2=sum(a*s)

// ---- packed f32x2 helpers (sm_100+) ----
__device__ __forceinline__ ull fma2_(ull a, ull b, ull c) {
    ull d; asm("fma.rn.f32x2 %0, %1, %2, %3;" : "=l"(d) : "l"(a), "l"(b), "l"(c)); return d;
}
__device__ __forceinline__ ull add2_(ull a, ull b) {
    ull d; asm("add.rn.f32x2 %0, %1, %2;" : "=l"(d) : "l"(a), "l"(b)); return d;
}
__device__ __forceinline__ float lo_(ull v) { return __uint_as_float((unsigned)(v & 0xFFFFFFFFu)); }
__device__ __forceinline__ float hi_(ull v) { return __uint_as_float((unsigned)(v >> 32)); }

#define NEG1_2 0xBF800000BF800000ULL
#define ABS2   0x7FFFFFFF7FFFFFFFULL

__device__ __forceinline__ float warp_sum(float v) {
#pragma unroll
    for (int o = 16; o > 0; o >>= 1) v += __shfl_xor_sync(0xFFFFFFFFu, v, o);
    return v;
}
__device__ __forceinline__ float warp_min(float v) {
#pragma unroll
    for (int o = 16; o > 0; o >>= 1) v = fminf(v, __shfl_xor_sync(0xFFFFFFFFu, v, o));
    return v;
}

// ---------------------------------------------------------------- K1: distances
// 64x64 tile per block, 256 threads, 4x4 register micro-tile, packed f32x2 accum.
#define TP 68
__global__ __launch_bounds__(256)
void k_dist(const float* __restrict__ zx, const float* __restrict__ zy) {
    __shared__ float xs[64 * TP];
    __shared__ float ys[64 * TP];
    __shared__ float smin[8];

    int tid = threadIdx.x;
    int tx = tid & 15, ty = tid >> 4;
    int bi = blockIdx.y << 6, bj = blockIdx.x << 6;
    int bid = blockIdx.y * 16 + blockIdx.x;

    // zero this block's 4-column slice of g_csum (consumed only by later k_sums)
    if (tid < 4) g_csum[bid * 4 + tid] = 0.0f;

    ull a0[4][4], a1[4][4];
#pragma unroll
    for (int i = 0; i < 4; i++)
#pragma unroll
        for (int j = 0; j < 4; j++) { a0[i][j] = 0ULL; a1[i][j] = 0ULL; }

    for (int kc = 0; kc < 2; kc++) {
        if (kc) __syncthreads();
#pragma unroll
        for (int l = tid; l < 1024; l += 256) {
            int r  = l >> 4;
            int dq = l & 15;
            int sw = (dq ^ ((r >> 2) & 15)) << 2;
            float4 vx = *reinterpret_cast<const float4*>(zx + (bi + r) * DIMK + kc * 64 + dq * 4);
            *reinterpret_cast<float4*>(&xs[r * TP + sw]) = vx;
            float4 vy = *reinterpret_cast<const float4*>(zy + (bj + r) * DIMK + kc * 64 + dq * 4);
            *reinterpret_cast<float4*>(&ys[r * TP + sw]) = vy;
        }
        __syncthreads();

#pragma unroll 4
        for (int dq = 0; dq < 16; dq++) {
            ulonglong2 av[4], bv[4];
            int gx = (dq ^ ty) << 2;
            int gy = (dq ^ tx) << 2;
#pragma unroll
            for (int ii = 0; ii < 4; ii++)
                av[ii] = *reinterpret_cast<const ulonglong2*>(&xs[(4 * ty + ii) * TP + gx]);
#pragma unroll
            for (int jj = 0; jj < 4; jj++)
                bv[jj] = *reinterpret_cast<const ulonglong2*>(&ys[(4 * tx + jj) * TP + gy]);
#pragma unroll
            for (int ii = 0; ii < 4; ii++)
#pragma unroll
                for (int jj = 0; jj < 4; jj++) {
                    ull d0 = fma2_(bv[jj].x, NEG1_2, av[ii].x);   // x - y (pair 0)
                    d0 &= ABS2;
                    a0[ii][jj] = add2_(a0[ii][jj], d0);
                    ull d1 = fma2_(bv[jj].y, NEG1_2, av[ii].y);   // pair 1
                    d1 &= ABS2;
                    a1[ii][jj] = add2_(a1[ii][jj], d1);
                }
        }
    }

    // combine packed lanes, write s = -acc, track block min distance
    float mymin = 3.4e38f;
    float accv[4][4];
#pragma unroll
    for (int ii = 0; ii < 4; ii++)
#pragma unroll
        for (int jj = 0; jj < 4; jj++) {
            float a = (lo_(a0[ii][jj]) + hi_(a0[ii][jj])) +
                      (lo_(a1[ii][jj]) + hi_(a1[ii][jj]));
            accv[ii][jj] = a;
            mymin = fminf(mymin, a);
        }
#pragma unroll
    for (int ii = 0; ii < 4; ii++) {
        float4 v = make_float4(-accv[ii][0], -accv[ii][1], -accv[ii][2], -accv[ii][3]);
        *reinterpret_cast<float4*>(&g_s[(bi + 4 * ty + ii) * NY + bj + 4 * tx]) = v;
    }

    mymin = warp_min(mymin);
    int lane = tid & 31, w = tid >> 5;
    if (lane == 0) smin[w] = mymin;
    __syncthreads();
    if (tid == 0) {
        float m = smin[0];
#pragma unroll
        for (int k = 1; k < 8; k++) m = fminf(m, smin[k]);
        g_bmax[bid] = m;        // plain write: one owner per slot, no init needed
    }
}

// ---------------------------------------------------------------- K2: fused row+col sumexp
// 128 blocks x 8 rows x 1024 cols. One exp per element serves both softmaxes
// (global shift M). Thread t owns cols [4t,4t+4).
__global__ __launch_bounds__(256) void k_sums() {
    int tid = threadIdx.x, lane = tid & 31, w = tid >> 5;
    __shared__ float smin[8];
    __shared__ float sM;
    __shared__ float rowsh[8][8];

    // reduce global min distance from 256 per-block partials
    float v = g_bmax[tid];
    v = warp_min(v);
    if (lane == 0) smin[w] = v;
    __syncthreads();
    if (tid == 0) {
        float m = smin[0];
#pragma unroll
        for (int k = 1; k < 8; k++) m = fminf(m, smin[k]);
        sM = m;
        if (blockIdx.x == 0) g_M = m;   // publish for k_final
    }
    __syncthreads();
    float mn = sM;                      // e = exp(s + mn), since M(max s) = -mn

    int r0 = blockIdx.x * 8;
    float4 cacc = make_float4(0.f, 0.f, 0.f, 0.f);
    float rp[8];
#pragma unroll
    for (int r = 0; r < 8; r++) {
        float4 s4 = *reinterpret_cast<const float4*>(&g_s[(r0 + r) * NY + 4 * tid]);
        float ex = __expf(s4.x + mn);
        float ey = __expf(s4.y + mn);
        float ez = __expf(s4.z + mn);
        float ew = __expf(s4.w + mn);
        cacc.x += ex; cacc.y += ey; cacc.z += ez; cacc.w += ew;
        rp[r] = (ex + ey) + (ez + ew);
    }
#pragma unroll
    for (int r = 0; r < 8; r++) {
        float t = warp_sum(rp[r]);
        if (lane == 0) rowsh[r][w] = t;
    }
    __syncthreads();
    if (tid < 8) {
        float t = rowsh[tid][0];
#pragma unroll
        for (int k = 1; k < 8; k++) t += rowsh[tid][k];
        g_rsum[r0 + tid] = t;
    }
    atomicAdd(&g_csum[4 * tid + 0], cacc.x);
    atomicAdd(&g_csum[4 * tid + 1], cacc.y);
    atomicAdd(&g_csum[4 * tid + 2], cacc.z);
    atomicAdd(&g_csum[4 * tid + 3], cacc.w);
}

// ---------------------------------------------------------------- K3: a = er+ec-er*ec; per-row partials
__global__ __launch_bounds__(256) void k_final() {
    int i = blockIdx.x, tid = threadIdx.x;
    float mn = g_M;
    float rinv = __fdividef(1.0f, g_rsum[i]);

    float4 s4 = *reinterpret_cast<const float4*>(&g_s[i * NY + 4 * tid]);
    float4 cs = *reinterpret_cast<const float4*>(&g_csum[4 * tid]);
    float ci_x = __fdividef(1.0f, cs.x);
    float ci_y = __fdividef(1.0f, cs.y);
    float ci_z = __fdividef(1.0f, cs.z);
    float ci_w = __fdividef(1.0f, cs.w);

    float p1 = 0.f, p2 = 0.f;
    {
        float e = __expf(s4.x + mn);
        float er = e * rinv, ec = e * ci_x;
        float a = er + ec - er * ec; p1 += a; p2 += a * s4.x;
    }
    {
        float e = __expf(s4.y + mn);
        float er = e * rinv, ec = e * ci_y;
        float a = er + ec - er * ec; p1 += a; p2 += a * s4.y;
    }
    {
        float e = __expf(s4.z + mn);
        float er = e * rinv, ec = e * ci_z;
        float a = er + ec - er * ec; p1 += a; p2 += a * s4.z;
    }
    {
        float e = __expf(s4.w + mn);
        float er = e * rinv, ec = e * ci_w;
        float a = er + ec - er * ec; p1 += a; p2 += a * s4.w;
    }

    __shared__ float sh1[8], sh2[8];
    int lane = tid & 31, w = tid >> 5;
    p1 = warp_sum(p1);
    p2 = warp_sum(p2);
    if (lane == 0) { sh1[w] = p1; sh2[w] = p2; }
    __syncthreads();
    if (tid == 0) {
        float a1 = 0.f, a2 = 0.f;
#pragma unroll
        for (int k = 0; k < 8; k++) { a1 += sh1[k]; a2 += sh2[k]; }
        g_p1[i] = a1;
        g_p2[i] = a2;
    }
}

// ---------------------------------------------------------------- K4: reduce partials + logits
__global__ __launch_bounds__(256) void k_out(const float* __restrict__ theta,
                                             const float* __restrict__ beta,
                                             float* __restrict__ out, int n) {
    int tid = threadIdx.x, lane = tid & 31, w = tid >> 5;
    float p1 = g_p1[tid] + g_p1[tid + 256] + g_p1[tid + 512] + g_p1[tid + 768];
    float p2 = g_p2[tid] + g_p2[tid + 256] + g_p2[tid + 512] + g_p2[tid + 768];
    __shared__ float sh1[8], sh2[8];
    __shared__ float sc;
    p1 = warp_sum(p1);
    p2 = warp_sum(p2);
    if (lane == 0) { sh1[w] = p1; sh2[w] = p2; }
    __syncthreads();
    if (tid == 0) {
        float S1 = 0.f, S2 = 0.f;
#pragma unroll
        for (int k = 0; k < 8; k++) { S1 += sh1[k]; S2 += sh2[k]; }
        sc = S2 / S1;
    }
    __syncthreads();
    if (tid < n && n <= 256) out[tid] = sc * theta[tid] + beta[tid];
}

// ---------------------------------------------------------------- launch
extern "C" void kernel_launch(void* const* d_in, const int* in_sizes, int n_in,
                              void* d_out, int out_size) {
    (void)n_in; (void)in_sizes;
    const float* zx    = (const float*)d_in[0];
    const float* zy    = (const float*)d_in[1];
    const float* theta = (const float*)d_in[2];
    const float* beta  = (const float*)d_in[3];
    float* out = (float*)d_out;

    dim3 g1(NY / 64, NX / 64);                 // 16 x 16 = 256 blocks
    k_dist<<<g1, 256>>>(zx, zy);
    k_sums<<<128, 256>>>();
    k_final<<<NX, 256>>>();
    k_out<<<1, 256>>>(theta, beta, out, out_size);
}

// round 6
// speedup vs baseline: 1.0409x; 1.0409x over previous
#include <cuda_runtime.h>
#include <cuda_bf16.h>

#define NXX 1024
#define NYY 1024
#define DIMK 128
#define NBLK 256

typedef unsigned long long ull;

// ---- scratch globals (no allocation; nothing needs per-replay re-init) ----
__device__ float    g_bmin[NBLK];            // per-block min distance (plain write)
__device__ float    g_rpart[NXX * 16];       // row-sum partials [row][bx]
__device__ float    g_cpart[NYY * 16];       // col-sum partials [col][by]
__device__ float    g_p1[NBLK], g_p2[NBLK];  // per-block S1/S2 partials
__device__ unsigned g_cnt[3];                // barrier arrival counters (self-resetting)
__device__ unsigned g_gen[3];                // barrier generations (monotonic, never reset)

// ---- packed f32x2 helpers (sm_100+) ----
__device__ __forceinline__ ull fma2_(ull a, ull b, ull c) {
    ull d; asm("fma.rn.f32x2 %0, %1, %2, %3;" : "=l"(d) : "l"(a), "l"(b), "l"(c)); return d;
}
__device__ __forceinline__ ull add2_(ull a, ull b) {
    ull d; asm("add.rn.f32x2 %0, %1, %2;" : "=l"(d) : "l"(a), "l"(b)); return d;
}
__device__ __forceinline__ float lo_(ull v) { return __uint_as_float((unsigned)(v & 0xFFFFFFFFu)); }
__device__ __forceinline__ float hi_(ull v) { return __uint_as_float((unsigned)(v >> 32)); }

#define NEG1_2 0xBF800000BF800000ULL
#define ABS2   0x7FFFFFFF7FFFFFFFULL

__device__ __forceinline__ float warp_sum(float v) {
#pragma unroll
    for (int o = 16; o > 0; o >>= 1) v += __shfl_xor_sync(0xFFFFFFFFu, v, o);
    return v;
}
__device__ __forceinline__ float warp_min(float v) {
#pragma unroll
    for (int o = 16; o > 0; o >>= 1) v = fminf(v, __shfl_xor_sync(0xFFFFFFFFu, v, o));
    return v;
}

// grid-wide barrier: read generation BEFORE arriving, so the release (which
// requires all arrivals, including ours) can never precede our snapshot.
__device__ __forceinline__ void grid_bar(int i) {
    __syncthreads();
    if (threadIdx.x == 0) {
        volatile unsigned* genp = (volatile unsigned*)&g_gen[i];
        unsigned start = *genp;
        __threadfence();
        unsigned my = atomicAdd(&g_cnt[i], 1u);
        if (my == NBLK - 1) {
            g_cnt[i] = 0;                 // safe: all arrivals are in
            __threadfence();
            atomicAdd(&g_gen[i], 1u);     // release
        } else {
            while (*genp == start) { }
            __threadfence();
        }
    }
    __syncthreads();
}

// ---------------------------------------------------------------- the kernel
#define TP 68
__global__ __launch_bounds__(256, 2)
void k_all(const float* __restrict__ zx, const float* __restrict__ zy,
           const float* __restrict__ theta, const float* __restrict__ beta,
           float* __restrict__ out, int nout) {
    __shared__ float SH[2 * 64 * TP];     // xs | ys ; reused as scratch later
    __shared__ float s_aux[72];
    float* xs = SH;
    float* ys = SH + 64 * TP;

    const int tid = threadIdx.x;
    const int lane = tid & 31, w = tid >> 5;
    const int tx = tid & 15, ty = tid >> 4;
    const int bid = blockIdx.x;
    const int bx = bid & 15, by = bid >> 4;
    const int bi = by << 6, bj = bx << 6;

    // ================= Phase 1: L1 distances (packed f32x2) =================
    ull acc[4][4];
#pragma unroll
    for (int i = 0; i < 4; i++)
#pragma unroll
        for (int j = 0; j < 4; j++) acc[i][j] = 0ULL;

    for (int kc = 0; kc < 2; kc++) {
        if (kc) __syncthreads();
#pragma unroll
        for (int l = tid; l < 1024; l += 256) {
            int r  = l >> 4;
            int dq = l & 15;
            int sw = (dq ^ ((r >> 2) & 15)) << 2;
            float4 vx = *reinterpret_cast<const float4*>(zx + (bi + r) * DIMK + kc * 64 + dq * 4);
            *reinterpret_cast<float4*>(&xs[r * TP + sw]) = vx;
            float4 vy = *reinterpret_cast<const float4*>(zy + (bj + r) * DIMK + kc * 64 + dq * 4);
            *reinterpret_cast<float4*>(&ys[r * TP + sw]) = vy;
        }
        __syncthreads();

#pragma unroll 4
        for (int dq = 0; dq < 16; dq++) {
            ulonglong2 av[4], bv[4];
            int gx = (dq ^ ty) << 2;
            int gy = (dq ^ tx) << 2;
#pragma unroll
            for (int ii = 0; ii < 4; ii++)
                av[ii] = *reinterpret_cast<const ulonglong2*>(&xs[(4 * ty + ii) * TP + gx]);
#pragma unroll
            for (int jj = 0; jj < 4; jj++)
                bv[jj] = *reinterpret_cast<const ulonglong2*>(&ys[(4 * tx + jj) * TP + gy]);
#pragma unroll
            for (int ii = 0; ii < 4; ii++)
#pragma unroll
                for (int jj = 0; jj < 4; jj++) {
                    ull d0 = fma2_(bv[jj].x, NEG1_2, av[ii].x) & ABS2;
                    ull d1 = fma2_(bv[jj].y, NEG1_2, av[ii].y) & ABS2;
                    acc[ii][jj] = add2_(acc[ii][jj], add2_(d0, d1));
                }
        }
    }

    // collapse packed pairs; track block min distance (max s = -min dist)
    float accv[4][4];
    float mymin = 3.4e38f;
#pragma unroll
    for (int ii = 0; ii < 4; ii++)
#pragma unroll
        for (int jj = 0; jj < 4; jj++) {
            float a = lo_(acc[ii][jj]) + hi_(acc[ii][jj]);
            accv[ii][jj] = a;
            mymin = fminf(mymin, a);
        }
    mymin = warp_min(mymin);
    __syncthreads();                       // xs/ys free from here
    if (lane == 0) s_aux[w] = mymin;
    __syncthreads();
    if (tid == 0) {
        float m = s_aux[0];
#pragma unroll
        for (int k = 1; k < 8; k++) m = fminf(m, s_aux[k]);
        g_bmin[bid] = m;
    }

    grid_bar(0);

    // ================= Phase 2: exp + row/col sum partials =================
    {
        float v = g_bmin[tid];             // 256 entries, one per thread
        v = warp_min(v);
        if (lane == 0) s_aux[w] = v;
        __syncthreads();
        if (tid == 0) {
            float m = s_aux[0];
#pragma unroll
            for (int k = 1; k < 8; k++) m = fminf(m, s_aux[k]);
            s_aux[64] = m;
        }
        __syncthreads();
    }
    const float mn = s_aux[64];            // e = exp(mn - dist) = exp(s - max_s)

    float e[4][4];
#pragma unroll
    for (int ii = 0; ii < 4; ii++)
#pragma unroll
        for (int jj = 0; jj < 4; jj++)
            e[ii][jj] = __expf(mn - accv[ii][jj]);

    // row partials: sum over jj then over the 16 threads sharing each row
#pragma unroll
    for (int ii = 0; ii < 4; ii++) {
        float r = (e[ii][0] + e[ii][1]) + (e[ii][2] + e[ii][3]);
#pragma unroll
        for (int o = 8; o > 0; o >>= 1) r += __shfl_xor_sync(0xFFFFFFFFu, r, o);
        if (tx == 0) g_rpart[(bi + 4 * ty + ii) * 16 + bx] = r;
    }

    // col partials via smem (reduce over ty)
    float* red = xs;                       // [64][17]
    __syncthreads();
#pragma unroll
    for (int jj = 0; jj < 4; jj++)
        red[(4 * tx + jj) * 17 + ty] = (e[0][jj] + e[1][jj]) + (e[2][jj] + e[3][jj]);
    __syncthreads();
    if (tid < 64) {
        float c = 0.0f;
#pragma unroll
        for (int k = 0; k < 16; k++) c += red[tid * 17 + k];
        g_cpart[(bj + tid) * 16 + by] = c;
    }

    grid_bar(1);

    // ================= Phase 3: a = er+ec-er*ec; block partials =================
    float* rs = ys;                        // [64] reciprocal row sums for rows bi..
    float* cs = ys + 64;                   // [64] reciprocal col sums for cols bj..
    if (tid < 64) {
        float t = 0.0f;
#pragma unroll
        for (int k = 0; k < 16; k++) t += g_rpart[(bi + tid) * 16 + k];
        rs[tid] = __fdividef(1.0f, t);
    } else if (tid < 128) {
        int c = tid - 64;
        float t = 0.0f;
#pragma unroll
        for (int k = 0; k < 16; k++) t += g_cpart[(bj + c) * 16 + k];
        cs[c] = __fdividef(1.0f, t);
    }
    __syncthreads();

    float csj[4];
#pragma unroll
    for (int jj = 0; jj < 4; jj++) csj[jj] = cs[4 * tx + jj];

    float p1 = 0.0f, p2 = 0.0f;
#pragma unroll
    for (int ii = 0; ii < 4; ii++) {
        float ri = rs[4 * ty + ii];
#pragma unroll
        for (int jj = 0; jj < 4; jj++) {
            float ev = e[ii][jj];
            float er = ev * ri;
            float ec = ev * csj[jj];
            float a = er + ec - er * ec;
            p1 += a;
            p2 -= a * accv[ii][jj];        // s = -dist
        }
    }
    p1 = warp_sum(p1);
    p2 = warp_sum(p2);
    __syncthreads();
    if (lane == 0) { s_aux[w] = p1; s_aux[8 + w] = p2; }
    __syncthreads();
    if (tid == 0) {
        float a1 = 0.f, a2 = 0.f;
#pragma unroll
        for (int k = 0; k < 8; k++) { a1 += s_aux[k]; a2 += s_aux[8 + k]; }
        g_p1[bid] = a1;
        g_p2[bid] = a2;
    }

    grid_bar(2);

    // ================= Phase 4: block 0 reduces + writes logits =================
    if (bid == 0) {
        float q1 = g_p1[tid];
        float q2 = g_p2[tid];
        q1 = warp_sum(q1);
        q2 = warp_sum(q2);
        __syncthreads();
        if (lane == 0) { s_aux[w] = q1; s_aux[8 + w] = q2; }
        __syncthreads();
        if (tid == 0) {
            float S1 = 0.f, S2 = 0.f;
#pragma unroll
            for (int k = 0; k < 8; k++) { S1 += s_aux[k]; S2 += s_aux[8 + k]; }
            s_aux[64] = S2 / S1;
        }
        __syncthreads();
        if (tid < nout && nout <= 256)
            out[tid] = s_aux[64] * theta[tid] + beta[tid];
    }
}

// ---------------------------------------------------------------- launch
extern "C" void kernel_launch(void* const* d_in, const int* in_sizes, int n_in,
                              void* d_out, int out_size) {
    (void)n_in; (void)in_sizes;
    const float* zx    = (const float*)d_in[0];
    const float* zy    = (const float*)d_in[1];
    const float* theta = (const float*)d_in[2];
    const float* beta  = (const float*)d_in[3];
    float* out = (float*)d_out;

    k_all<<<NBLK, 256>>>(zx, zy, theta, beta, out, out_size);
}